// round 1
// baseline (speedup 1.0000x reference)
#include <cuda_runtime.h>

// LIF constant-current encoder.
// x: [N] fp32 (N = 512*512). out: voltages [128*N] then spikes [128*N], fp32.
// v_{t+1} = v + 0.1*(x - v); z = (v > 1); v = z ? 0 : v; store v, z per step.

#define SEQ_LENGTH 128
#define ALPHA 0.1f   // DT * TAU_MEM_INV
#define V_TH 1.0f

__global__ __launch_bounds__(256)
void lif_encoder_kernel(const float* __restrict__ x,
                        float* __restrict__ out,
                        int n4 /* N/4 */, int n /* N */) {
    int i = blockIdx.x * blockDim.x + threadIdx.x;
    if (i >= n4) return;

    const float4* x4 = reinterpret_cast<const float4*>(x);
    float4 xv = x4[i];

    float4 v = make_float4(0.f, 0.f, 0.f, 0.f);

    // voltages at out[0 .. 128*n), spikes at out[128*n .. 256*n)
    float4* vp = reinterpret_cast<float4*>(out) + i;
    float4* zp = reinterpret_cast<float4*>(out + (size_t)SEQ_LENGTH * n) + i;

    #pragma unroll 4
    for (int t = 0; t < SEQ_LENGTH; ++t) {
        // integrate
        v.x = fmaf(ALPHA, xv.x - v.x, v.x);
        v.y = fmaf(ALPHA, xv.y - v.y, v.y);
        v.z = fmaf(ALPHA, xv.z - v.z, v.z);
        v.w = fmaf(ALPHA, xv.w - v.w, v.w);

        float4 z;
        z.x = (v.x > V_TH) ? 1.f : 0.f;
        z.y = (v.y > V_TH) ? 1.f : 0.f;
        z.z = (v.z > V_TH) ? 1.f : 0.f;
        z.w = (v.w > V_TH) ? 1.f : 0.f;

        // reset (v_reset = 0)
        v.x = (z.x != 0.f) ? 0.f : v.x;
        v.y = (z.y != 0.f) ? 0.f : v.y;
        v.z = (z.z != 0.f) ? 0.f : v.z;
        v.w = (z.w != 0.f) ? 0.f : v.w;

        *vp = v;
        *zp = z;
        vp += n4;
        zp += n4;
    }
}

extern "C" void kernel_launch(void* const* d_in, const int* in_sizes, int n_in,
                              void* d_out, int out_size) {
    const float* x = (const float*)d_in[0];
    float* out = (float*)d_out;
    int n = in_sizes[0];       // 262144
    int n4 = n / 4;            // 65536

    int block = 256;
    int grid = (n4 + block - 1) / block;
    lif_encoder_kernel<<<grid, block>>>(x, out, n4, n);
}

// round 2
// speedup vs baseline: 1.0657x; 1.0657x over previous
#include <cuda_runtime.h>

// LIF constant-current encoder, time-split for occupancy.
// x: [N] fp32 (N = 512*512). out: voltages [128*N] then spikes [128*N], fp32.
// Recurrence: v = v + 0.1*(x - v); z = (v > 1); v = z ? 0 : v.
// Stores never feed back into v, so each block replays the recurrence from
// t=0 in registers (compute-only) and stores only its 32-step time chunk.
// This quadruples the number of store-issuing CTAs (occupancy 22% -> ~86%).

#define SEQ_LENGTH 128
#define CHUNK      32
#define NCHUNKS    (SEQ_LENGTH / CHUNK)
#define ALPHA      0.1f   // DT * TAU_MEM_INV
#define V_TH       1.0f

__device__ __forceinline__ void lif_step(float4& v, const float4& xv, float4& z) {
    v.x = fmaf(ALPHA, xv.x - v.x, v.x);
    v.y = fmaf(ALPHA, xv.y - v.y, v.y);
    v.z = fmaf(ALPHA, xv.z - v.z, v.z);
    v.w = fmaf(ALPHA, xv.w - v.w, v.w);
    z.x = (v.x > V_TH) ? 1.f : 0.f;
    z.y = (v.y > V_TH) ? 1.f : 0.f;
    z.z = (v.z > V_TH) ? 1.f : 0.f;
    z.w = (v.w > V_TH) ? 1.f : 0.f;
    v.x = (z.x != 0.f) ? 0.f : v.x;
    v.y = (z.y != 0.f) ? 0.f : v.y;
    v.z = (z.z != 0.f) ? 0.f : v.z;
    v.w = (z.w != 0.f) ? 0.f : v.w;
}

__global__ __launch_bounds__(256)
void lif_encoder_kernel(const float* __restrict__ x,
                        float* __restrict__ out,
                        int n4 /* N/4 */, int n /* N */) {
    int i = blockIdx.x * blockDim.x + threadIdx.x;
    if (i >= n4) return;
    int chunk = blockIdx.y;          // 0..3, time chunk
    int t0 = chunk * CHUNK;

    float4 xv = reinterpret_cast<const float4*>(x)[i];
    float4 v = make_float4(0.f, 0.f, 0.f, 0.f);
    float4 z;

    // Replay recurrence up to the start of this chunk (registers only).
    #pragma unroll 8
    for (int t = 0; t < t0; ++t)
        lif_step(v, xv, z);

    float4* vp = reinterpret_cast<float4*>(out) + (size_t)t0 * n4 + i;
    float4* zp = reinterpret_cast<float4*>(out + (size_t)SEQ_LENGTH * n)
                 + (size_t)t0 * n4 + i;

    #pragma unroll 4
    for (int t = 0; t < CHUNK; ++t) {
        lif_step(v, xv, z);
        __stcs(vp, v);
        __stcs(zp, z);
        vp += n4;
        zp += n4;
    }
}

extern "C" void kernel_launch(void* const* d_in, const int* in_sizes, int n_in,
                              void* d_out, int out_size) {
    const float* x = (const float*)d_in[0];
    float* out = (float*)d_out;
    int n = in_sizes[0];       // 262144
    int n4 = n / 4;            // 65536

    dim3 block(256);
    dim3 grid((n4 + 255) / 256, NCHUNKS);
    lif_encoder_kernel<<<grid, block>>>(x, out, n4, n);
}

// round 3
// speedup vs baseline: 1.0904x; 1.0232x over previous
#include <cuda_runtime.h>

// LIF constant-current encoder, time-split (8 chunks of 16 steps).
// x: [N] fp32 (N = 512*512). out: voltages [128*N] then spikes [128*N], fp32.
// v = v + 0.1*(x - v); z = (v > 1); v = z ? 0 : v.
// Each CTA replays the recurrence from t=0 in registers (compute-only, idle
// FMA pipe) and stores only its 16-step chunk -> 2048 CTAs of store issuers.

#define SEQ_LENGTH 128
#define CHUNK      16
#define NCHUNKS    (SEQ_LENGTH / CHUNK)
#define ALPHA      0.1f   // DT * TAU_MEM_INV
#define V_TH       1.0f

// Replay-only step: no spike materialization (4 instr/elem).
__device__ __forceinline__ void lif_step_nv(float4& v, const float4& xv) {
    v.x = fmaf(ALPHA, xv.x - v.x, v.x);
    v.y = fmaf(ALPHA, xv.y - v.y, v.y);
    v.z = fmaf(ALPHA, xv.z - v.z, v.z);
    v.w = fmaf(ALPHA, xv.w - v.w, v.w);
    v.x = (v.x > V_TH) ? 0.f : v.x;
    v.y = (v.y > V_TH) ? 0.f : v.y;
    v.z = (v.z > V_TH) ? 0.f : v.z;
    v.w = (v.w > V_TH) ? 0.f : v.w;
}

__device__ __forceinline__ void lif_step(float4& v, const float4& xv, float4& z) {
    v.x = fmaf(ALPHA, xv.x - v.x, v.x);
    v.y = fmaf(ALPHA, xv.y - v.y, v.y);
    v.z = fmaf(ALPHA, xv.z - v.z, v.z);
    v.w = fmaf(ALPHA, xv.w - v.w, v.w);
    z.x = (v.x > V_TH) ? 1.f : 0.f;
    z.y = (v.y > V_TH) ? 1.f : 0.f;
    z.z = (v.z > V_TH) ? 1.f : 0.f;
    z.w = (v.w > V_TH) ? 1.f : 0.f;
    v.x = (z.x != 0.f) ? 0.f : v.x;
    v.y = (z.y != 0.f) ? 0.f : v.y;
    v.z = (z.z != 0.f) ? 0.f : v.z;
    v.w = (z.w != 0.f) ? 0.f : v.w;
}

__global__ __launch_bounds__(256)
void lif_encoder_kernel(const float* __restrict__ x,
                        float* __restrict__ out,
                        int n4 /* N/4 */, int n /* N */) {
    int i = blockIdx.x * blockDim.x + threadIdx.x;
    if (i >= n4) return;
    int t0 = blockIdx.y * CHUNK;

    float4 xv = reinterpret_cast<const float4*>(x)[i];
    float4 v = make_float4(0.f, 0.f, 0.f, 0.f);
    float4 z;

    // Replay recurrence up to the start of this chunk (registers only).
    #pragma unroll 8
    for (int t = 0; t < t0; ++t)
        lif_step_nv(v, xv);

    float4* vp = reinterpret_cast<float4*>(out) + (size_t)t0 * n4 + i;
    float4* zp = reinterpret_cast<float4*>(out + (size_t)SEQ_LENGTH * n)
                 + (size_t)t0 * n4 + i;

    #pragma unroll
    for (int t = 0; t < CHUNK; ++t) {
        lif_step(v, xv, z);
        __stcs(vp, v);
        __stcs(zp, z);
        vp += n4;
        zp += n4;
    }
}

extern "C" void kernel_launch(void* const* d_in, const int* in_sizes, int n_in,
                              void* d_out, int out_size) {
    const float* x = (const float*)d_in[0];
    float* out = (float*)d_out;
    int n = in_sizes[0];       // 262144
    int n4 = n / 4;            // 65536

    dim3 block(256);
    dim3 grid((n4 + 255) / 256, NCHUNKS);
    lif_encoder_kernel<<<grid, block>>>(x, out, n4, n);
}